// round 2
// baseline (speedup 1.0000x reference)
#include <cuda_runtime.h>

#define HIDDEN   1024
#define SEQ      784
#define BATCH    512
#define NTHREADS 256
#define NWARPS   (NTHREADS / 32)
#define E        (HIDDEN / NTHREADS)   // 4 hidden states per thread

// Accurate fast tanh: ex2.approx (~2 ulp) + fast divide. Abs error ~1e-7,
// safe through the 784-step recurrence (tanh.approx.f32's ~5e-4 would not be).
__device__ __forceinline__ float fast_tanh(float x) {
    float xc = fminf(fmaxf(x, -15.f), 15.f);   // avoid exp overflow -> NaN
    float y = xc * 2.885390081777927f;         // 2/ln(2): e^{2x} = 2^{y}
    float ex;
    asm("ex2.approx.ftz.f32 %0, %1;" : "=f"(ex) : "f"(y));
    return __fdividef(ex - 1.f, ex + 1.f);
}

// One block per batch element. The HiPPO bilinear step
//   h <- tanh( (I-cA)^{-1} [ (I+cA) h + u*step*P ] )
// collapses (A diagonal + rank-1 semiseparable) to ONE linear scan over i:
//   r_{i+1} = alpha_i r_i + w_i,  w_i = gamma_i h_i + delta_i u   (r_0 = 0)
//   x_i     = (g_i h_i + u*step*P_i - c P_i r_i) / D_i
//   h_i     = tanh(x_i)
// with P_i = sqrt(1+2i), D_i = 1+c(1+i), g_i = 1-c(1+i),
//      alpha_i = (1-c i)/D_i, gamma_i = 2 P_i/D_i, delta_i = step P_i^2/D_i.
__global__ void __launch_bounds__(NTHREADS, 4)
ssm_scan_kernel(const float* __restrict__ x,
                const float* __restrict__ C,
                const float* __restrict__ W,
                const float* __restrict__ bias,
                float* __restrict__ out)
{
    __shared__ float xs[SEQ];
    __shared__ float wta[2][NWARPS];   // warp-total affine 'a' (double-buffered by t parity)
    __shared__ float wtb[2][NWARPS];   // warp-total affine 'b'
    __shared__ float red[NWARPS];

    const int tid  = threadIdx.x;
    const int lane = tid & 31;
    const int wid  = tid >> 5;
    const int bidx = blockIdx.x;

    // Stage this sequence's inputs in smem (784 floats).
    for (int i = tid; i < SEQ; i += NTHREADS) xs[i] = x[bidx * SEQ + i];

    // Per-element constants, built in double (matches reference's fp64 HiPPO setup).
    float alf[E], gam[E], dlt[E], A1[E], A2[E], A3[E], h[E], w[E];
    {
        const double step = 1.0 / (double)SEQ;
        const double c    = 0.5 * step;
        #pragma unroll
        for (int e = 0; e < E; ++e) {
            const int    i = tid * E + e;
            const double q = (double)i;
            const double P = sqrt(1.0 + 2.0 * q);
            const double D = 1.0 + c * (1.0 + q);
            alf[e] = (float)((1.0 - c * q) / D);
            gam[e] = (float)(2.0 * P / D);
            dlt[e] = (float)(step * P * P / D);
            A1[e]  = (float)((1.0 - c * (1.0 + q)) / D);  // g_i / D_i
            A2[e]  = (float)(step * P / D);               // (u term) / D_i
            A3[e]  = (float)(c * P / D);                  // (c P_i) / D_i
            h[e]   = 0.f;
        }
    }
    __syncthreads();

    for (int t = 0; t < SEQ; ++t) {
        const float u = xs[t];

        // ---- thread-local composition of E affine maps r -> alpha*r + w ----
        // w_e are independent (pure ILP); cb/ca chains are only E=4 deep.
        float ca = 1.f, cb = 0.f;
        #pragma unroll
        for (int e = 0; e < E; ++e) {
            w[e] = fmaf(gam[e], h[e], u * dlt[e]);
            cb = fmaf(alf[e], cb, w[e]);
            ca *= alf[e];
        }

        // ---- warp inclusive scan of affine pairs (Hillis-Steele over lanes) ----
        float sa = ca, sb = cb;
        #pragma unroll
        for (int d = 1; d < 32; d <<= 1) {
            float ra = __shfl_up_sync(0xffffffffu, sa, d);
            float rb = __shfl_up_sync(0xffffffffu, sb, d);
            if (lane >= d) { sb = fmaf(sa, rb, sb); sa *= ra; }
        }
        // exclusive-within-warp = shifted inclusive (identity at lane 0)
        float ea = __shfl_up_sync(0xffffffffu, sa, 1);
        float eb = __shfl_up_sync(0xffffffffu, sb, 1);
        if (lane == 0) { ea = 1.f; eb = 0.f; }

        const int par = t & 1;
        if (lane == 31) { wta[par][wid] = sa; wtb[par][wid] = sb; }
        __syncthreads();   // the ONLY block barrier per step (parity double-buffer)

        // cross-warp exclusive composition (<= NWARPS-1 composes, uniform per warp)
        float gb = 0.f;
        #pragma unroll
        for (int w2 = 0; w2 < NWARPS - 1; ++w2) {
            if (w2 < wid) gb = fmaf(wta[par][w2], gb, wtb[par][w2]);
        }
        // r at this thread's first element: apply (threadExcl o warpsBefore) to r_0 = 0
        float r = fmaf(ea, gb, eb);

        // ---- apply: r-chain is one FMA per element; xv/tanh fully off-chain ----
        #pragma unroll
        for (int e = 0; e < E; ++e) {
            float xv = fmaf(A1[e], h[e], fmaf(-A3[e], r, u * A2[e]));
            r = fmaf(alf[e], r, w[e]);     // r_{i+1} = alpha_i r_i + w_i
            h[e] = fast_tanh(xv);
        }
    }

    // ---- epilogue: y_b = C . h ; out[b][o] = y_b * W[o] + bias[o] ----
    float partial = 0.f;
    #pragma unroll
    for (int e = 0; e < E; ++e)
        partial = fmaf(__ldg(&C[tid * E + e]), h[e], partial);
    #pragma unroll
    for (int d = 16; d > 0; d >>= 1)
        partial += __shfl_down_sync(0xffffffffu, partial, d);
    if (lane == 0) red[wid] = partial;
    __syncthreads();
    if (tid == 0) {
        float y = 0.f;
        #pragma unroll
        for (int w2 = 0; w2 < NWARPS; ++w2) y += red[w2];
        #pragma unroll
        for (int o = 0; o < 10; ++o)
            out[bidx * 10 + o] = fmaf(y, W[o], bias[o]);
    }
}

extern "C" void kernel_launch(void* const* d_in, const int* in_sizes, int n_in,
                              void* d_out, int out_size) {
    const float* x    = (const float*)d_in[0];   // (512, 784, 1)
    const float* C    = (const float*)d_in[1];   // (1, 1024)
    const float* W    = (const float*)d_in[2];   // (1, 10)
    const float* bias = (const float*)d_in[3];   // (10,)
    float* out        = (float*)d_out;           // (512, 10)
    ssm_scan_kernel<<<BATCH, NTHREADS>>>(x, C, W, bias, out);
}

// round 4
// speedup vs baseline: 1.6912x; 1.6912x over previous
#include <cuda_runtime.h>

#define HIDDEN   1024
#define SEQ      784
#define BATCH    512
#define NTHREADS 128
#define NWARPS   (NTHREADS / 32)
#define E        (HIDDEN / NTHREADS)   // 8 hidden states per thread

// tanh(x) = 1 - 2/(e^{2x}+1). Saturates safely at +-inf with approx ex2/rcp
// (ex2->Inf => rcp->0 => +1 ; ex2->0 => rcp(1)=1 => -1), so NO clamps needed.
// Abs error ~1e-7 (2 ulp class) -- safe through the 784-step recurrence.
__device__ __forceinline__ float fast_tanh(float x) {
    float e, rc;
    asm("ex2.approx.ftz.f32 %0, %1;" : "=f"(e) : "f"(x * 2.885390081777927f));
    asm("rcp.approx.ftz.f32 %0, %1;" : "=f"(rc) : "f"(e + 1.0f));
    return fmaf(-2.0f, rc, 1.0f);
}

// One block per batch element. HiPPO bilinear step collapses (A is diagonal +
// rank-1 semiseparable) to ONE linear scan over hidden index i:
//   r_{i+1} = alf_i r_i + w_i,  w_i = gam_i h_i + dlt_i u     (r_0 = 0)
//   x_i     = A1_i h_i + A2_i u - A3_i r_i ;  h_i = tanh(x_i)
// CRUCIAL: all multiplicative scan coefficients (alf products) are constant in
// time, so the 'a' half of the parallel scan is PRECOMPUTED once:
//   saL[k] : this lane's accumulated 'a' entering scan level k
//   eaC    : lane-exclusive 'a' prefix within the warp
//   cw[w2] : cross-warp composition weights (gb = sum cw[w2]*wtb[w2])
// Per time-step the scan runs on 'b' only: 6 shfl + ~6 FMA total.
__global__ void __launch_bounds__(NTHREADS, 4)
ssm_scan_kernel(const float* __restrict__ x,
                const float* __restrict__ C,
                const float* __restrict__ W,
                const float* __restrict__ bias,
                float* __restrict__ out)
{
    __shared__ float xs[SEQ];
    __shared__ float wtb[2][NWARPS];   // warp-total 'b' (double-buffered by t parity)
    __shared__ float wtot[NWARPS];     // init-time warp 'a' totals
    __shared__ float red[NWARPS];

    const int tid  = threadIdx.x;
    const int lane = tid & 31;
    const int wid  = tid >> 5;
    const int bidx = blockIdx.x;

    for (int i = tid; i < SEQ; i += NTHREADS) xs[i] = x[bidx * SEQ + i];

    // ---- per-element constants, built in double (matches reference fp64 HiPPO) ----
    float alf[E], gam[E], dlt[E], A1[E], A2[E], A3[E], Ks[E], h[E], w[E];
    {
        const double step = 1.0 / (double)SEQ;
        const double c    = 0.5 * step;
        #pragma unroll
        for (int e = 0; e < E; ++e) {
            const int    i = tid * E + e;
            const double q = (double)i;
            const double P = sqrt(1.0 + 2.0 * q);
            const double D = 1.0 + c * (1.0 + q);
            alf[e] = (float)((1.0 - c * q) / D);
            gam[e] = (float)(2.0 * P / D);
            dlt[e] = (float)(step * P * P / D);
            A1[e]  = (float)((1.0 - c * (1.0 + q)) / D);
            A2[e]  = (float)(step * P / D);
            A3[e]  = (float)(c * P / D);
            h[e]   = 0.f;
        }
        // Ks[e] = prod_{j>e} alf[j]  (suffix products for the cb dot product)
        float p = 1.f;
        #pragma unroll
        for (int e = E - 1; e >= 0; --e) { Ks[e] = p; p *= alf[e]; }
    }

    // ---- one-time scan of the constant 'a' components ----
    float Athr = 1.f;
    #pragma unroll
    for (int e = 0; e < E; ++e) Athr *= alf[e];

    float saL[5];
    float sa = Athr;
    #pragma unroll
    for (int k = 0; k < 5; ++k) {
        saL[k] = sa;
        float ra = __shfl_up_sync(0xffffffffu, sa, 1 << k);
        if (lane >= (1 << k)) sa *= ra;
    }
    float eaC = __shfl_up_sync(0xffffffffu, sa, 1);
    if (lane == 0) eaC = 1.f;
    if (lane == 31) wtot[wid] = sa;
    __syncthreads();

    // cw[w2] = prod_{w3=w2+1}^{wid-1} wtot[w3] for w2 < wid, else 0.
    float cw[NWARPS - 1];
    {
        float p = 1.f;
        #pragma unroll
        for (int w3 = NWARPS - 2; w3 >= 0; --w3) {
            if (w3 < wid) { cw[w3] = p; p *= wtot[w3]; }
            else           cw[w3] = 0.f;
        }
    }
    __syncthreads();

    // =========================== main time loop ===========================
    #pragma unroll 2
    for (int t = 0; t < SEQ; ++t) {
        const float u = xs[t];

        // ---- thread-local: w_e (independent) and cb = sum Ks_e * w_e (tree) ----
        #pragma unroll
        for (int e = 0; e < E; ++e)
            w[e] = fmaf(gam[e], h[e], u * dlt[e]);
        float cb0 = 0.f, cb1 = 0.f;
        #pragma unroll
        for (int e = 0; e < E; e += 2) {
            cb0 = fmaf(Ks[e],     w[e],     cb0);
            cb1 = fmaf(Ks[e + 1], w[e + 1], cb1);
        }
        float sb = cb0 + cb1;

        // ---- warp inclusive scan on 'b' only ('a' ladder is precomputed) ----
        #pragma unroll
        for (int k = 0; k < 5; ++k) {
            float rb = __shfl_up_sync(0xffffffffu, sb, 1 << k);
            if (lane >= (1 << k)) sb = fmaf(saL[k], rb, sb);
        }
        float eb = __shfl_up_sync(0xffffffffu, sb, 1);
        if (lane == 0) eb = 0.f;

        const int par = t & 1;               // folds to a constant under unroll 2
        if (lane == 31) wtb[par][wid] = sb;
        __syncthreads();            // the ONLY block barrier per step

        // cross-warp: constant-weighted SUM (no chain)
        float gb = 0.f;
        #pragma unroll
        for (int w2 = 0; w2 < NWARPS - 1; ++w2)
            gb = fmaf(cw[w2], wtb[par][w2], gb);

        float r = fmaf(eaC, gb, eb);  // r at this thread's first element

        // ---- apply: 1-FMA r-chain; xv/tanh hang off it with full ILP ----
        #pragma unroll
        for (int e = 0; e < E; ++e) {
            float xv = fmaf(A1[e], h[e], fmaf(-A3[e], r, u * A2[e]));
            r = fmaf(alf[e], r, w[e]);
            h[e] = fast_tanh(xv);
        }
    }

    // ---- epilogue: y_b = C . h ; out[b][o] = y_b * W[o] + bias[o] ----
    float partial = 0.f;
    #pragma unroll
    for (int e = 0; e < E; ++e)
        partial = fmaf(__ldg(&C[tid * E + e]), h[e], partial);
    #pragma unroll
    for (int d = 16; d > 0; d >>= 1)
        partial += __shfl_down_sync(0xffffffffu, partial, d);
    if (lane == 0) red[wid] = partial;
    __syncthreads();
    if (tid == 0) {
        float y = 0.f;
        #pragma unroll
        for (int w2 = 0; w2 < NWARPS; ++w2) y += red[w2];
        #pragma unroll
        for (int o = 0; o < 10; ++o)
            out[bidx * 10 + o] = fmaf(y, W[o], bias[o]);
    }
}

extern "C" void kernel_launch(void* const* d_in, const int* in_sizes, int n_in,
                              void* d_out, int out_size) {
    const float* x    = (const float*)d_in[0];   // (512, 784, 1)
    const float* C    = (const float*)d_in[1];   // (1, 1024)
    const float* W    = (const float*)d_in[2];   // (1, 10)
    const float* bias = (const float*)d_in[3];   // (10,)
    float* out        = (float*)d_out;           // (512, 10)
    ssm_scan_kernel<<<BATCH, NTHREADS>>>(x, C, W, bias, out);
}